// round 16
// baseline (speedup 1.0000x reference)
#include <cuda_runtime.h>
#include <cuda_fp16.h>
#include <cstdint>

// Problem constants (fixed instance)
#define N1c 2000     // landmarks
#define NNc 4000     // total nodes
#define NPADc 4096   // padded node count
#define Dc 63        // feature dim
#define Ec 64        // embedding dim
#define Hc 8         // heads
#define KNNc 5
#define MPADc 2048   // padded col count for d2 matrix

// -------- device scratch (no allocations allowed) --------
__device__ __half g_Ah[(size_t)Hc * NPADc * Ec];   // [h][n][e] normalized a (fp16)
__device__ __half g_Bh[(size_t)Hc * NPADc * Ec];   // [h][n][e] normalized b (fp16)
__device__ float g_sq[N1c];                        // row squared norms of lm_X
__device__ float g_XT[Ec * MPADc];                 // lm_X transposed [64][2048]
__device__ float g_d2[(size_t)N1c * MPADc];        // pairwise squared distances

__device__ __forceinline__ uint32_t smem_u32(const void* p) {
    uint32_t a;
    asm("{ .reg .u64 t; cvta.to.shared.u64 t, %1; cvt.u32.u64 %0, t; }"
        : "=r"(a) : "l"(p));
    return a;
}

// -------- cp.async helpers --------
__device__ __forceinline__ void cp16(uint32_t s_dst, const void* g_src) {
    asm volatile("cp.async.cg.shared.global [%0], [%1], 16;"
                 :: "r"(s_dst), "l"(g_src));
}
__device__ __forceinline__ void cp_commit() {
    asm volatile("cp.async.commit_group;");
}
template <int N>
__device__ __forceinline__ void cp_wait() {
    asm volatile("cp.async.wait_group %0;" :: "n"(N));
}

// fast tanh (MUFU.TANH)
__device__ __forceinline__ float tanh_fast(float x) {
    float t;
    asm("tanh.approx.f32 %0, %1;" : "=f"(t) : "f"(x));
    return t;
}

// =====================================================================
// teacher fill, TARGET ROWS ONLY (rows 2000..3999): lm cols = 1, tg = 0.
// Landmark rows (0..1999) are written by topk_kernel.
// =====================================================================
__global__ void fill_tg_kernel(float* __restrict__ t) {
    int j = (blockIdx.x * 256 + threadIdx.x) * 4;
    int i = N1c + blockIdx.y;
    if (j < NNc) {
        float v = (j < N1c) ? 1.0f : 0.0f;
        *(float4*)&t[(size_t)i * NNc + j] = make_float4(v, v, v, v);
    }
}

// =====================================================================
// squared norms of landmark rows
// =====================================================================
__global__ void sq_kernel(const float* __restrict__ lm_X) {
    int n = blockIdx.x * blockDim.x + threadIdx.x;
    if (n < N1c) {
        float s = 0.f;
        #pragma unroll
        for (int k = 0; k < Dc; k++) {
            float x = lm_X[n * Dc + k];
            s = fmaf(x, x, s);
        }
        g_sq[n] = s;
    }
}

// =====================================================================
// transpose lm_X -> g_XT [64][2048]
// =====================================================================
__global__ void xt_kernel(const float* __restrict__ lm_X) {
    int idx = blockIdx.x * 256 + threadIdx.x;
    if (idx < Ec * MPADc) {
        int k = idx / MPADc;
        int n = idx % MPADc;
        g_XT[idx] = (k < Dc && n < N1c) ? lm_X[n * Dc + k] : 0.f;
    }
}

// =====================================================================
// embedding + per-head normalized vectors (fp16 output)
// =====================================================================
__global__ void __launch_bounds__(256) embed_kernel(
        const float* __restrict__ lm_X,
        const float* __restrict__ tg_X,
        const float* __restrict__ lm_delay,
        const float* __restrict__ tg_delay,
        const float* __restrict__ W_emb,
        const float* __restrict__ b_emb,
        const float* __restrict__ w1,
        const float* __restrict__ w2) {
    __shared__ float Wsh[Ec * 65];
    __shared__ float w1T[Hc * Ec];
    __shared__ float w2T[Hc * Ec];
    __shared__ float feat[8][Ec];

    const int tid = threadIdx.x;
    const int lane = tid & 31;
    const int wp = tid >> 5;
    const int n = blockIdx.x * 8 + wp;

    for (int idx = tid; idx < Ec * Ec; idx += 256)
        Wsh[(idx >> 6) * 65 + (idx & 63)] = W_emb[idx];
    for (int idx = tid; idx < Hc * Ec; idx += 256) {
        int h = idx & 7, j = idx >> 3;
        w1T[h * Ec + j] = w1[idx];
        w2T[h * Ec + j] = w2[idx];
    }

    const bool pad = (n >= NNc);
    if (!pad) {
        const float* src = (n < N1c) ? lm_X + (size_t)n * Dc
                                     : tg_X + (size_t)(n - N1c) * Dc;
        float dly = (n < N1c) ? lm_delay[n] : tg_delay[n - N1c];
        feat[wp][lane] = src[lane];
        feat[wp][lane + 32] = (lane < 31) ? src[lane + 32] : dly;
    }
    __syncthreads();

    if (pad) {
        const __half2 z = __floats2half2_rn(0.f, 0.f);
        #pragma unroll
        for (int h = 0; h < Hc; h++) {
            *(__half2*)&g_Ah[((size_t)h * NPADc + n) * Ec + 2 * lane] = z;
            *(__half2*)&g_Bh[((size_t)h * NPADc + n) * Ec + 2 * lane] = z;
        }
        return;
    }

    const int j0 = 2 * lane, j1 = 2 * lane + 1;
    float e0 = b_emb[j0], e1 = b_emb[j1];
    const float* W0 = &Wsh[j0 * 65];
    const float* W1 = &Wsh[j1 * 65];
    #pragma unroll
    for (int k = 0; k < Ec; k++) {
        float f = feat[wp][k];
        e0 = fmaf(W0[k], f, e0);
        e1 = fmaf(W1[k], f, e1);
    }

    float a0[Hc], a1[Hc], b0[Hc], b1[Hc], va[Hc], vb[Hc];
    #pragma unroll
    for (int h = 0; h < Hc; h++) {
        float2 wa = *(const float2*)&w1T[h * Ec + j0];
        float2 wb = *(const float2*)&w2T[h * Ec + j0];
        a0[h] = e0 * wa.x; a1[h] = e1 * wa.y;
        b0[h] = e0 * wb.x; b1[h] = e1 * wb.y;
        va[h] = fmaf(a0[h], a0[h], a1[h] * a1[h]);
        vb[h] = fmaf(b0[h], b0[h], b1[h] * b1[h]);
    }
    #pragma unroll
    for (int o = 16; o > 0; o >>= 1) {
        #pragma unroll
        for (int h = 0; h < Hc; h++) {
            va[h] += __shfl_xor_sync(0xffffffffu, va[h], o);
            vb[h] += __shfl_xor_sync(0xffffffffu, vb[h], o);
        }
    }
    #pragma unroll
    for (int h = 0; h < Hc; h++) {
        float ra = rsqrtf(va[h]);
        float rb = rsqrtf(vb[h]);
        *(__half2*)&g_Ah[((size_t)h * NPADc + n) * Ec + j0] =
            __floats2half2_rn(a0[h] * ra, a1[h] * ra);
        *(__half2*)&g_Bh[((size_t)h * NPADc + n) * Ec + j0] =
            __floats2half2_rn(b0[h] * rb, b1[h] * rb);
    }
}

// =====================================================================
// d2 GEMM v2: 128x128 upper-tri tiles (136 CTAs), 8x8 per-thread tile.
// Same fp32 FMA accumulation order over k -> bit-identical d2 values.
// Mirror via 2-pass staged transpose in the (freed) As region.
// =====================================================================
#define D2_AS_FLOATS (64 * 128)
#define D2_BS_STRIDE 132
#define D2_SMEM ((D2_AS_FLOATS + 64 * D2_BS_STRIDE) * 4)   // 66560 bytes

__global__ void __launch_bounds__(256) d2_kernel() {
    extern __shared__ float ds[];
    float* As = ds;                         // [64][128]
    float* Bs = ds + D2_AS_FLOATS;          // [64][132]

    const int tid = threadIdx.x;
    const int tx = tid >> 4, ty = tid & 15;

    int bid = blockIdx.x;
    int bx = (int)((sqrtf(8.f * (float)bid + 1.f) - 1.f) * 0.5f);
    while ((bx + 1) * (bx + 2) / 2 <= bid) bx++;
    while (bx * (bx + 1) / 2 > bid) bx--;
    int by = bid - bx * (bx + 1) / 2;

    const int n0 = by * 128;
    const int m0 = bx * 128;

    #pragma unroll
    for (int p = 0; p < 8; p++) {
        int lin = p * 1024 + tid * 4;
        int k = lin >> 7, c = lin & 127;
        *(float4*)&As[k * 128 + c] = *(const float4*)&g_XT[k * MPADc + n0 + c];
        *(float4*)&Bs[k * D2_BS_STRIDE + c] = *(const float4*)&g_XT[k * MPADc + m0 + c];
    }
    __syncthreads();

    float dot[8][8];
    #pragma unroll
    for (int i = 0; i < 8; i++)
        #pragma unroll
        for (int j = 0; j < 8; j++) dot[i][j] = 0.f;

    #pragma unroll 4
    for (int k = 0; k < Ec; k++) {
        float a[8], b[8];
        *(float4*)&a[0] = *(float4*)&As[k * 128 + tx * 8];
        *(float4*)&a[4] = *(float4*)&As[k * 128 + tx * 8 + 4];
        *(float4*)&b[0] = *(float4*)&Bs[k * D2_BS_STRIDE + ty * 8];
        *(float4*)&b[4] = *(float4*)&Bs[k * D2_BS_STRIDE + ty * 8 + 4];
        #pragma unroll
        for (int i = 0; i < 8; i++)
            #pragma unroll
            for (int j = 0; j < 8; j++)
                dot[i][j] = fmaf(a[i], b[j], dot[i][j]);
    }

    const float INF = __int_as_float(0x7f800000);
    float v[8][8];
    #pragma unroll
    for (int i = 0; i < 8; i++) {
        int nn = n0 + tx * 8 + i;
        float sqn = (nn < N1c) ? g_sq[nn] : 0.f;
        #pragma unroll
        for (int j = 0; j < 8; j++) {
            int mm = m0 + ty * 8 + j;
            float val = INF;
            if (nn < N1c && mm < N1c && mm != nn)
                val = fmaxf(sqn + g_sq[mm] - 2.f * dot[i][j], 0.f);
            v[i][j] = val;
        }
    }

    // normal write: rows nn, cols m0 + ty*8 .. +7 (two float4)
    #pragma unroll
    for (int i = 0; i < 8; i++) {
        int nn = n0 + tx * 8 + i;
        if (nn < N1c) {
            *(float4*)&g_d2[(size_t)nn * MPADc + m0 + ty * 8] =
                make_float4(v[i][0], v[i][1], v[i][2], v[i][3]);
            *(float4*)&g_d2[(size_t)nn * MPADc + m0 + ty * 8 + 4] =
                make_float4(v[i][4], v[i][5], v[i][6], v[i][7]);
        }
    }

    if (bx == by) return;

    // mirror: 2-pass staged transpose through the As region (stride 132)
    float* St = ds;
    #pragma unroll 1
    for (int p = 0; p < 2; p++) {
        __syncthreads();   // previous users of St / previous pass done
        if ((ty >> 3) == p) {
            #pragma unroll
            for (int j = 0; j < 8; j++) {
                int mloc = (ty & 7) * 8 + j;   // 0..63 within this half
                #pragma unroll
                for (int i = 0; i < 8; i++)
                    St[mloc * D2_BS_STRIDE + tx * 8 + i] = v[i][j];
            }
        }
        __syncthreads();
        #pragma unroll
        for (int q = 0; q < 8; q++) {
            int lin = q * 1024 + tid * 4;
            int r = lin >> 7, c = lin & 127;
            int mm = m0 + p * 64 + r;
            if (mm < N1c)
                *(float4*)&g_d2[(size_t)mm * MPADc + n0 + c] =
                    *(float4*)&St[r * D2_BS_STRIDE + c];
        }
    }
}

// =====================================================================
// top-5 per row from d2; y_pred + OWNS its teacher row
// =====================================================================
__global__ void topk_kernel(const float* __restrict__ lm_Y,
                            float* __restrict__ y_pred,
                            float* __restrict__ teacher) {
    __shared__ unsigned long long wmin[8];
    __shared__ unsigned long long swin;
    const int n = blockIdx.x;
    const int tid = threadIdx.x;
    const int lane = tid & 31;
    const int wp = tid >> 5;
    const float INF = __int_as_float(0x7f800000);

    // ---- write this landmark's full teacher row (before scatter) ----
    {
        float* row = teacher + (size_t)n * NNc;
        #pragma unroll
        for (int i = 0; i < 4; i++) {
            int c = (i * 256 + tid) * 4;
            if (c < NNc) {
                float v = (c >= N1c) ? 1.0f : 0.0f;
                *(float4*)&row[c] = make_float4(v, v, v, v);
            }
        }
    }

    float bd[KNNc];
    int   bi[KNNc];
    #pragma unroll
    for (int t = 0; t < KNNc; t++) { bd[t] = INF; bi[t] = 0; }

    #pragma unroll
    for (int it = 0; it < 8; it++) {
        int m = it * 256 + tid;
        float d2 = g_d2[(size_t)n * MPADc + m];
        if (d2 < bd[KNNc - 1]) {
            bd[KNNc - 1] = d2; bi[KNNc - 1] = m;
            #pragma unroll
            for (int t = KNNc - 1; t > 0; t--) {
                if (bd[t] < bd[t - 1]) {
                    float td = bd[t]; bd[t] = bd[t - 1]; bd[t - 1] = td;
                    int   ti = bi[t]; bi[t] = bi[t - 1]; bi[t - 1] = ti;
                }
            }
        }
    }
    __syncthreads();

    float y0 = 0.f, y1 = 0.f;
    #pragma unroll 1
    for (int r = 0; r < KNNc; r++) {
        unsigned long long key =
            (((unsigned long long)__float_as_uint(bd[0])) << 32) | (unsigned)bi[0];
        unsigned long long wk = key;
        #pragma unroll
        for (int o = 16; o > 0; o >>= 1) {
            unsigned long long t = __shfl_xor_sync(0xffffffffu, wk, o);
            if (t < wk) wk = t;
        }
        if (lane == 0) wmin[wp] = wk;
        __syncthreads();
        if (tid == 0) {
            unsigned long long m = wmin[0];
            #pragma unroll
            for (int i = 1; i < 8; i++) if (wmin[i] < m) m = wmin[i];
            swin = m;
        }
        __syncthreads();
        unsigned long long win = swin;
        int wm = (int)(win & 0xffffffffull);
        if (key == win) {
            #pragma unroll
            for (int t = 0; t < KNNc - 1; t++) { bd[t] = bd[t + 1]; bi[t] = bi[t + 1]; }
            bd[KNNc - 1] = INF; bi[KNNc - 1] = 0;
        }
        if (tid == 0) {
            teacher[(size_t)n * NNc + wm] = 1.0f;
            y0 += lm_Y[wm * 2 + 0];
            y1 += lm_Y[wm * 2 + 1];
        }
    }
    if (tid == 0) {
        y_pred[n * 2 + 0] = y0 * 0.2f;
        y_pred[n * 2 + 1] = y1 * 0.2f;
    }
}

// =====================================================================
// HMMA adjacency kernel (R10 champion config): 64x64 tile, 128 threads
// (2x2 warps of 32x32), 4 CTAs/SM, 2-stage double buffer, fp16 acc,
// sigmoid via MUFU tanh.
// =====================================================================
#define A_BYTES 8192                // 64 rows x 128B
#define B_BYTES 8192                // 64 rows x 128B
#define STAGE_BYTES (A_BYTES + B_BYTES)

__device__ __forceinline__ void ldsm_x4(uint32_t* r, uint32_t addr) {
    asm volatile("ldmatrix.sync.aligned.m8n8.x4.shared.b16 {%0,%1,%2,%3}, [%4];"
                 : "=r"(r[0]), "=r"(r[1]), "=r"(r[2]), "=r"(r[3]) : "r"(addr));
}
__device__ __forceinline__ void mma_f16acc(uint32_t* c, const uint32_t* a,
                                           const uint32_t* b) {
    asm volatile(
        "mma.sync.aligned.m16n8k16.row.col.f16.f16.f16.f16 "
        "{%0,%1}, {%2,%3,%4,%5}, {%6,%7}, {%0,%1};"
        : "+r"(c[0]), "+r"(c[1])
        : "r"(a[0]), "r"(a[1]), "r"(a[2]), "r"(a[3]), "r"(b[0]), "r"(b[1]));
}

__global__ void __launch_bounds__(128, 4) adj_mm_kernel(float* __restrict__ adj) {
    extern __shared__ char dsm[];
    uint32_t dbase = smem_u32(dsm);
    uint32_t abase = (dbase + 1023u) & ~1023u;

    const int tid = threadIdx.x;
    const int lane = tid & 31;
    const int wid = tid >> 5;
    const int wm = wid & 1;
    const int wn = wid >> 1;
    const int n0 = blockIdx.y * 64;
    const int m0 = blockIdx.x * 64;

    auto load_stage = [&](uint32_t sbase, int h) {
        const char* asrc = (const char*)(g_Ah + ((size_t)h * NPADc + n0) * Ec);
        const char* bsrc = (const char*)(g_Bh + ((size_t)h * NPADc + m0) * Ec);
        #pragma unroll
        for (int i = 0; i < 4; i++) {
            int c = tid + i * 128;
            int r = c >> 3, s = c & 7;
            uint32_t off = (uint32_t)r * 128 + s * 16;
            uint32_t sw = off ^ ((off >> 3) & 0x70);
            cp16(sbase + sw, asrc + (size_t)r * 128 + s * 16);
            cp16(sbase + A_BYTES + sw, bsrc + (size_t)r * 128 + s * 16);
        }
        cp_commit();
    };

    const int a_row = wm * 32 + (lane & 15);
    const int a_sh  = lane >> 4;
    const int b_m   = lane >> 3;
    const int b_row = wn * 32 + (b_m >> 1) * 8 + (lane & 7);
    const int b_sh  = b_m & 1;

    float acc[2][4][4];
    #pragma unroll
    for (int mt = 0; mt < 2; mt++)
        #pragma unroll
        for (int nt = 0; nt < 4; nt++)
            #pragma unroll
            for (int r = 0; r < 4; r++) acc[mt][nt][r] = 0.f;

    load_stage(abase, 0);

    #pragma unroll 1
    for (int h = 0; h < Hc; h++) {
        const int p = h & 1;
        if (h < Hc - 1) {
            load_stage(abase + (1 - p) * STAGE_BYTES, h + 1);
            cp_wait<1>();
        } else {
            cp_wait<0>();
        }
        __syncthreads();

        const uint32_t Ab = abase + p * STAGE_BYTES;
        const uint32_t Bb = Ab + A_BYTES;

        uint32_t sim[2][4][2];
        #pragma unroll
        for (int mt = 0; mt < 2; mt++)
            #pragma unroll
            for (int nt = 0; nt < 4; nt++) {
                sim[mt][nt][0] = 0u;
                sim[mt][nt][1] = 0u;
            }

        #pragma unroll
        for (int k = 0; k < 4; k++) {
            uint32_t afr[2][4];
            #pragma unroll
            for (int mt = 0; mt < 2; mt++) {
                uint32_t off = (uint32_t)(a_row + mt * 16) * 128 + (k * 2 + a_sh) * 16;
                uint32_t sw = off ^ ((off >> 3) & 0x70);
                ldsm_x4(afr[mt], Ab + sw);
            }
            uint32_t bfr[4][2];
            #pragma unroll
            for (int ntp = 0; ntp < 2; ntp++) {
                uint32_t off = (uint32_t)(b_row + ntp * 16) * 128 + (k * 2 + b_sh) * 16;
                uint32_t sw = off ^ ((off >> 3) & 0x70);
                uint32_t r4[4];
                ldsm_x4(r4, Bb + sw);
                bfr[ntp * 2 + 0][0] = r4[0]; bfr[ntp * 2 + 0][1] = r4[1];
                bfr[ntp * 2 + 1][0] = r4[2]; bfr[ntp * 2 + 1][1] = r4[3];
            }
            #pragma unroll
            for (int mt = 0; mt < 2; mt++)
                #pragma unroll
                for (int nt = 0; nt < 4; nt++)
                    mma_f16acc(sim[mt][nt], afr[mt], bfr[nt]);
        }

        #pragma unroll
        for (int mt = 0; mt < 2; mt++)
            #pragma unroll
            for (int nt = 0; nt < 4; nt++) {
                #pragma unroll
                for (int half = 0; half < 2; half++) {
                    float2 f = __half22float2(
                        *reinterpret_cast<__half2*>(&sim[mt][nt][half]));
                    float t0 = tanh_fast(f.x * 0.5f);
                    float t1 = tanh_fast(f.y * 0.5f);
                    acc[mt][nt][half * 2 + 0] =
                        fmaf(0.5f, t0, acc[mt][nt][half * 2 + 0]);
                    acc[mt][nt][half * 2 + 1] =
                        fmaf(0.5f, t1, acc[mt][nt][half * 2 + 1]);
                }
            }

        __syncthreads();
    }

    const int g = lane >> 2;
    const int tig = lane & 3;
    #pragma unroll
    for (int mt = 0; mt < 2; mt++) {
        int gn0 = n0 + wm * 32 + mt * 16 + g;
        #pragma unroll
        for (int nt = 0; nt < 4; nt++) {
            int gm = m0 + wn * 32 + nt * 8 + tig * 2;
            if (gm < NNc) {
                if (gn0 < NNc) {
                    float2 v = make_float2(fmaf(acc[mt][nt][0], 0.125f, 0.5f),
                                           fmaf(acc[mt][nt][1], 0.125f, 0.5f));
                    *(float2*)&adj[(size_t)gn0 * NNc + gm] = v;
                }
                if (gn0 + 8 < NNc) {
                    float2 v = make_float2(fmaf(acc[mt][nt][2], 0.125f, 0.5f),
                                           fmaf(acc[mt][nt][3], 0.125f, 0.5f));
                    *(float2*)&adj[(size_t)(gn0 + 8) * NNc + gm] = v;
                }
            }
        }
    }
}

// =====================================================================
// launch: fork-join; side branch independent (topk owns lm teacher rows)
// =====================================================================
extern "C" void kernel_launch(void* const* d_in, const int* in_sizes, int n_in,
                              void* d_out, int out_size) {
    (void)in_sizes; (void)n_in; (void)out_size;
    const float* lm_X     = (const float*)d_in[0];
    const float* lm_Y     = (const float*)d_in[1];
    const float* tg_X     = (const float*)d_in[2];
    const float* lm_delay = (const float*)d_in[4];
    const float* tg_delay = (const float*)d_in[5];
    const float* W_emb    = (const float*)d_in[6];
    const float* b_emb    = (const float*)d_in[7];
    const float* w1       = (const float*)d_in[8];
    const float* w2       = (const float*)d_in[9];

    float* out     = (float*)d_out;
    float* y_pred  = out;                       // [2000, 2]
    float* adj     = out + 4000;                // [4000, 4000]
    float* teacher = adj + (size_t)NNc * NNc;   // [4000, 4000]

    static bool init = false;
    static cudaStream_t s1, s2;
    static cudaEvent_t ef, e_s1, e_join;
    const int ADJ_SMEM = 2 * STAGE_BYTES + 1024;  // 33792
    if (!init) {
        cudaFuncSetAttribute(adj_mm_kernel,
                             cudaFuncAttributeMaxDynamicSharedMemorySize, ADJ_SMEM);
        cudaFuncSetAttribute(d2_kernel,
                             cudaFuncAttributeMaxDynamicSharedMemorySize, D2_SMEM);
        cudaStreamCreateWithFlags(&s1, cudaStreamNonBlocking);
        cudaStreamCreateWithFlags(&s2, cudaStreamNonBlocking);
        cudaEventCreateWithFlags(&ef,     cudaEventDisableTiming);
        cudaEventCreateWithFlags(&e_s1,   cudaEventDisableTiming);
        cudaEventCreateWithFlags(&e_join, cudaEventDisableTiming);
        init = true;
    }

    // fork
    cudaEventRecord(ef, 0);
    cudaStreamWaitEvent(s1, ef, 0);
    cudaStreamWaitEvent(s2, ef, 0);

    // (0) embedding (default stream; adj depends on it)
    embed_kernel<<<512, 256>>>(lm_X, tg_X, lm_delay, tg_delay,
                               W_emb, b_emb, w1, w2);
    // knn branch on s2: sq -> xt -> d2(v2) -> topk
    sq_kernel<<<8, 256, 0, s2>>>(lm_X);
    xt_kernel<<<(Ec * MPADc + 255) / 256, 256, 0, s2>>>(lm_X);
    d2_kernel<<<136, 256, D2_SMEM, s2>>>();
    topk_kernel<<<N1c, 256, 0, s2>>>(lm_Y, y_pred, teacher);
    cudaEventRecord(e_join, s2);
    // teacher target-rows fill on s1 (fully independent)
    fill_tg_kernel<<<dim3(4, N1c), 256, 0, s1>>>(teacher);
    cudaEventRecord(e_s1, s1);
    // big adjacency GEMM — last, fills in behind side work
    adj_mm_kernel<<<dim3(63, 63), 128, ADJ_SMEM>>>(adj);

    // join
    cudaStreamWaitEvent(0, e_join, 0);
    cudaStreamWaitEvent(0, e_s1, 0);
}

// round 17
// speedup vs baseline: 1.0350x; 1.0350x over previous
#include <cuda_runtime.h>
#include <cuda_fp16.h>
#include <cstdint>

// Problem constants (fixed instance)
#define N1c 2000     // landmarks
#define NNc 4000     // total nodes
#define NPADc 4096   // padded node count
#define Dc 63        // feature dim
#define Ec 64        // embedding dim
#define Hc 8         // heads
#define KNNc 5
#define MPADc 2048   // padded col count for d2 matrix

// -------- device scratch (no allocations allowed) --------
__device__ __half g_Ah[(size_t)Hc * NPADc * Ec];   // [h][n][e] normalized a (fp16)
__device__ __half g_Bh[(size_t)Hc * NPADc * Ec];   // [h][n][e] normalized b (fp16)
__device__ float g_sq[N1c];                        // row squared norms of lm_X
__device__ float g_XT[Ec * MPADc];                 // lm_X transposed [64][2048]
__device__ float g_d2[(size_t)N1c * MPADc];        // pairwise squared distances

__device__ __forceinline__ uint32_t smem_u32(const void* p) {
    uint32_t a;
    asm("{ .reg .u64 t; cvta.to.shared.u64 t, %1; cvt.u32.u64 %0, t; }"
        : "=r"(a) : "l"(p));
    return a;
}

// -------- cp.async helpers --------
__device__ __forceinline__ void cp16(uint32_t s_dst, const void* g_src) {
    asm volatile("cp.async.cg.shared.global [%0], [%1], 16;"
                 :: "r"(s_dst), "l"(g_src));
}
__device__ __forceinline__ void cp_commit() {
    asm volatile("cp.async.commit_group;");
}
template <int N>
__device__ __forceinline__ void cp_wait() {
    asm volatile("cp.async.wait_group %0;" :: "n"(N));
}

// fast tanh (MUFU.TANH)
__device__ __forceinline__ float tanh_fast(float x) {
    float t;
    asm("tanh.approx.f32 %0, %1;" : "=f"(t) : "f"(x));
    return t;
}

// =====================================================================
// squared norms of landmark rows
// =====================================================================
__global__ void sq_kernel(const float* __restrict__ lm_X) {
    int n = blockIdx.x * blockDim.x + threadIdx.x;
    if (n < N1c) {
        float s = 0.f;
        #pragma unroll
        for (int k = 0; k < Dc; k++) {
            float x = lm_X[n * Dc + k];
            s = fmaf(x, x, s);
        }
        g_sq[n] = s;
    }
}

// =====================================================================
// transpose lm_X -> g_XT [64][2048]
// =====================================================================
__global__ void xt_kernel(const float* __restrict__ lm_X) {
    int idx = blockIdx.x * 256 + threadIdx.x;
    if (idx < Ec * MPADc) {
        int k = idx / MPADc;
        int n = idx % MPADc;
        g_XT[idx] = (k < Dc && n < N1c) ? lm_X[n * Dc + k] : 0.f;
    }
}

// =====================================================================
// embedding + per-head normalized vectors (fp16 output)
// =====================================================================
__global__ void __launch_bounds__(256) embed_kernel(
        const float* __restrict__ lm_X,
        const float* __restrict__ tg_X,
        const float* __restrict__ lm_delay,
        const float* __restrict__ tg_delay,
        const float* __restrict__ W_emb,
        const float* __restrict__ b_emb,
        const float* __restrict__ w1,
        const float* __restrict__ w2) {
    __shared__ float Wsh[Ec * 65];
    __shared__ float w1T[Hc * Ec];
    __shared__ float w2T[Hc * Ec];
    __shared__ float feat[8][Ec];

    const int tid = threadIdx.x;
    const int lane = tid & 31;
    const int wp = tid >> 5;
    const int n = blockIdx.x * 8 + wp;

    for (int idx = tid; idx < Ec * Ec; idx += 256)
        Wsh[(idx >> 6) * 65 + (idx & 63)] = W_emb[idx];
    for (int idx = tid; idx < Hc * Ec; idx += 256) {
        int h = idx & 7, j = idx >> 3;
        w1T[h * Ec + j] = w1[idx];
        w2T[h * Ec + j] = w2[idx];
    }

    const bool pad = (n >= NNc);
    if (!pad) {
        const float* src = (n < N1c) ? lm_X + (size_t)n * Dc
                                     : tg_X + (size_t)(n - N1c) * Dc;
        float dly = (n < N1c) ? lm_delay[n] : tg_delay[n - N1c];
        feat[wp][lane] = src[lane];
        feat[wp][lane + 32] = (lane < 31) ? src[lane + 32] : dly;
    }
    __syncthreads();

    if (pad) {
        const __half2 z = __floats2half2_rn(0.f, 0.f);
        #pragma unroll
        for (int h = 0; h < Hc; h++) {
            *(__half2*)&g_Ah[((size_t)h * NPADc + n) * Ec + 2 * lane] = z;
            *(__half2*)&g_Bh[((size_t)h * NPADc + n) * Ec + 2 * lane] = z;
        }
        return;
    }

    const int j0 = 2 * lane, j1 = 2 * lane + 1;
    float e0 = b_emb[j0], e1 = b_emb[j1];
    const float* W0 = &Wsh[j0 * 65];
    const float* W1 = &Wsh[j1 * 65];
    #pragma unroll
    for (int k = 0; k < Ec; k++) {
        float f = feat[wp][k];
        e0 = fmaf(W0[k], f, e0);
        e1 = fmaf(W1[k], f, e1);
    }

    float a0[Hc], a1[Hc], b0[Hc], b1[Hc], va[Hc], vb[Hc];
    #pragma unroll
    for (int h = 0; h < Hc; h++) {
        float2 wa = *(const float2*)&w1T[h * Ec + j0];
        float2 wb = *(const float2*)&w2T[h * Ec + j0];
        a0[h] = e0 * wa.x; a1[h] = e1 * wa.y;
        b0[h] = e0 * wb.x; b1[h] = e1 * wb.y;
        va[h] = fmaf(a0[h], a0[h], a1[h] * a1[h]);
        vb[h] = fmaf(b0[h], b0[h], b1[h] * b1[h]);
    }
    #pragma unroll
    for (int o = 16; o > 0; o >>= 1) {
        #pragma unroll
        for (int h = 0; h < Hc; h++) {
            va[h] += __shfl_xor_sync(0xffffffffu, va[h], o);
            vb[h] += __shfl_xor_sync(0xffffffffu, vb[h], o);
        }
    }
    #pragma unroll
    for (int h = 0; h < Hc; h++) {
        float ra = rsqrtf(va[h]);
        float rb = rsqrtf(vb[h]);
        *(__half2*)&g_Ah[((size_t)h * NPADc + n) * Ec + j0] =
            __floats2half2_rn(a0[h] * ra, a1[h] * ra);
        *(__half2*)&g_Bh[((size_t)h * NPADc + n) * Ec + j0] =
            __floats2half2_rn(b0[h] * rb, b1[h] * rb);
    }
}

// =====================================================================
// d2 GEMM (R15 proven version): 64x64 upper-tri tiles, float4 smem loads
// =====================================================================
__global__ void __launch_bounds__(256) d2_kernel() {
    __shared__ float As[Ec][64];
    __shared__ float Bs[Ec][68];   // stride 68 keeps float4 alignment

    const int tid = threadIdx.x;
    const int tx = tid >> 4, ty = tid & 15;

    int bid = blockIdx.x;
    int bx = (int)((sqrtf(8.f * (float)bid + 1.f) - 1.f) * 0.5f);
    while ((bx + 1) * (bx + 2) / 2 <= bid) bx++;
    while (bx * (bx + 1) / 2 > bid) bx--;
    int by = bid - bx * (bx + 1) / 2;

    const int n0 = by * 64;
    const int m0 = bx * 64;

    #pragma unroll
    for (int p = 0; p < 16; p++) {
        int idx = p * 256 + tid;
        int k = idx >> 6, r = idx & 63;
        As[k][r] = g_XT[k * MPADc + n0 + r];
        Bs[k][r] = g_XT[k * MPADc + m0 + r];
    }
    __syncthreads();

    float dot[4][4];
    #pragma unroll
    for (int i = 0; i < 4; i++)
        #pragma unroll
        for (int j = 0; j < 4; j++) dot[i][j] = 0.f;

    #pragma unroll 16
    for (int k = 0; k < Ec; k++) {
        float4 a4 = *(const float4*)&As[k][tx * 4];
        float4 b4 = *(const float4*)&Bs[k][ty * 4];
        float a[4] = {a4.x, a4.y, a4.z, a4.w};
        float b[4] = {b4.x, b4.y, b4.z, b4.w};
        #pragma unroll
        for (int i = 0; i < 4; i++)
            #pragma unroll
            for (int j = 0; j < 4; j++)
                dot[i][j] = fmaf(a[i], b[j], dot[i][j]);
    }

    const float INF = __int_as_float(0x7f800000);
    float v[4][4];
    #pragma unroll
    for (int i = 0; i < 4; i++) {
        int nn = n0 + tx * 4 + i;
        float sqn = (nn < N1c) ? g_sq[nn] : 0.f;
        #pragma unroll
        for (int j = 0; j < 4; j++) {
            int mm = m0 + ty * 4 + j;
            float val = INF;
            if (nn < N1c && mm < N1c && mm != nn)
                val = fmaxf(sqn + g_sq[mm] - 2.f * dot[i][j], 0.f);
            v[i][j] = val;
        }
    }

    #pragma unroll
    for (int i = 0; i < 4; i++) {
        int nn = n0 + tx * 4 + i;
        if (nn < N1c)
            *(float4*)&g_d2[(size_t)nn * MPADc + m0 + ty * 4] =
                make_float4(v[i][0], v[i][1], v[i][2], v[i][3]);
    }

    if (bx == by) return;

    __syncthreads();
    #pragma unroll
    for (int i = 0; i < 4; i++)
        #pragma unroll
        for (int j = 0; j < 4; j++)
            Bs[tx * 4 + i][ty * 4 + j] = v[i][j];
    __syncthreads();

    #pragma unroll
    for (int i = 0; i < 4; i++) {
        int mm = m0 + tx * 4 + i;
        if (mm < N1c) {
            float4 o;
            o.x = Bs[ty * 4 + 0][tx * 4 + i];
            o.y = Bs[ty * 4 + 1][tx * 4 + i];
            o.z = Bs[ty * 4 + 2][tx * 4 + i];
            o.w = Bs[ty * 4 + 3][tx * 4 + i];
            *(float4*)&g_d2[(size_t)mm * MPADc + n0 + ty * 4] = o;
        }
    }
}

// =====================================================================
// top-5 per row from d2; y_pred + OWNS its teacher row
// =====================================================================
__global__ void topk_kernel(const float* __restrict__ lm_Y,
                            float* __restrict__ y_pred,
                            float* __restrict__ teacher) {
    __shared__ unsigned long long wmin[8];
    __shared__ unsigned long long swin;
    const int n = blockIdx.x;
    const int tid = threadIdx.x;
    const int lane = tid & 31;
    const int wp = tid >> 5;
    const float INF = __int_as_float(0x7f800000);

    // ---- write this landmark's full teacher row (before scatter) ----
    {
        float* row = teacher + (size_t)n * NNc;
        #pragma unroll
        for (int i = 0; i < 4; i++) {
            int c = (i * 256 + tid) * 4;
            if (c < NNc) {
                float v = (c >= N1c) ? 1.0f : 0.0f;
                *(float4*)&row[c] = make_float4(v, v, v, v);
            }
        }
    }

    float bd[KNNc];
    int   bi[KNNc];
    #pragma unroll
    for (int t = 0; t < KNNc; t++) { bd[t] = INF; bi[t] = 0; }

    #pragma unroll
    for (int it = 0; it < 8; it++) {
        int m = it * 256 + tid;
        float d2 = g_d2[(size_t)n * MPADc + m];
        if (d2 < bd[KNNc - 1]) {
            bd[KNNc - 1] = d2; bi[KNNc - 1] = m;
            #pragma unroll
            for (int t = KNNc - 1; t > 0; t--) {
                if (bd[t] < bd[t - 1]) {
                    float td = bd[t]; bd[t] = bd[t - 1]; bd[t - 1] = td;
                    int   ti = bi[t]; bi[t] = bi[t - 1]; bi[t - 1] = ti;
                }
            }
        }
    }
    __syncthreads();

    float y0 = 0.f, y1 = 0.f;
    #pragma unroll 1
    for (int r = 0; r < KNNc; r++) {
        unsigned long long key =
            (((unsigned long long)__float_as_uint(bd[0])) << 32) | (unsigned)bi[0];
        unsigned long long wk = key;
        #pragma unroll
        for (int o = 16; o > 0; o >>= 1) {
            unsigned long long t = __shfl_xor_sync(0xffffffffu, wk, o);
            if (t < wk) wk = t;
        }
        if (lane == 0) wmin[wp] = wk;
        __syncthreads();
        if (tid == 0) {
            unsigned long long m = wmin[0];
            #pragma unroll
            for (int i = 1; i < 8; i++) if (wmin[i] < m) m = wmin[i];
            swin = m;
        }
        __syncthreads();
        unsigned long long win = swin;
        int wm = (int)(win & 0xffffffffull);
        if (key == win) {
            #pragma unroll
            for (int t = 0; t < KNNc - 1; t++) { bd[t] = bd[t + 1]; bi[t] = bi[t + 1]; }
            bd[KNNc - 1] = INF; bi[KNNc - 1] = 0;
        }
        if (tid == 0) {
            teacher[(size_t)n * NNc + wm] = 1.0f;
            y0 += lm_Y[wm * 2 + 0];
            y1 += lm_Y[wm * 2 + 1];
        }
    }
    if (tid == 0) {
        y_pred[n * 2 + 0] = y0 * 0.2f;
        y_pred[n * 2 + 1] = y1 * 0.2f;
    }
}

// =====================================================================
// HMMA adjacency kernel: 64x64 tile, 128 threads, 4 CTAs/SM, 2-stage
// double buffer, fp16 acc, MUFU tanh sigmoid.
// EPILOGUE ALSO WRITES the teacher target rows (gn >= N1c): constant
// pattern (col < N1c ? 1 : 0) — replaces the fill_tg kernel for free
// (adj is DRAM-idle). N1c even + gm even => no float2 straddle.
// =====================================================================
#define A_BYTES 8192                // 64 rows x 128B
#define B_BYTES 8192                // 64 rows x 128B
#define STAGE_BYTES (A_BYTES + B_BYTES)

__device__ __forceinline__ void ldsm_x4(uint32_t* r, uint32_t addr) {
    asm volatile("ldmatrix.sync.aligned.m8n8.x4.shared.b16 {%0,%1,%2,%3}, [%4];"
                 : "=r"(r[0]), "=r"(r[1]), "=r"(r[2]), "=r"(r[3]) : "r"(addr));
}
__device__ __forceinline__ void mma_f16acc(uint32_t* c, const uint32_t* a,
                                           const uint32_t* b) {
    asm volatile(
        "mma.sync.aligned.m16n8k16.row.col.f16.f16.f16.f16 "
        "{%0,%1}, {%2,%3,%4,%5}, {%6,%7}, {%0,%1};"
        : "+r"(c[0]), "+r"(c[1])
        : "r"(a[0]), "r"(a[1]), "r"(a[2]), "r"(a[3]), "r"(b[0]), "r"(b[1]));
}

__global__ void __launch_bounds__(128, 4) adj_mm_kernel(float* __restrict__ adj,
                                                        float* __restrict__ teacher) {
    extern __shared__ char dsm[];
    uint32_t dbase = smem_u32(dsm);
    uint32_t abase = (dbase + 1023u) & ~1023u;

    const int tid = threadIdx.x;
    const int lane = tid & 31;
    const int wid = tid >> 5;
    const int wm = wid & 1;
    const int wn = wid >> 1;
    const int n0 = blockIdx.y * 64;
    const int m0 = blockIdx.x * 64;

    auto load_stage = [&](uint32_t sbase, int h) {
        const char* asrc = (const char*)(g_Ah + ((size_t)h * NPADc + n0) * Ec);
        const char* bsrc = (const char*)(g_Bh + ((size_t)h * NPADc + m0) * Ec);
        #pragma unroll
        for (int i = 0; i < 4; i++) {
            int c = tid + i * 128;
            int r = c >> 3, s = c & 7;
            uint32_t off = (uint32_t)r * 128 + s * 16;
            uint32_t sw = off ^ ((off >> 3) & 0x70);
            cp16(sbase + sw, asrc + (size_t)r * 128 + s * 16);
            cp16(sbase + A_BYTES + sw, bsrc + (size_t)r * 128 + s * 16);
        }
        cp_commit();
    };

    const int a_row = wm * 32 + (lane & 15);
    const int a_sh  = lane >> 4;
    const int b_m   = lane >> 3;
    const int b_row = wn * 32 + (b_m >> 1) * 8 + (lane & 7);
    const int b_sh  = b_m & 1;

    float acc[2][4][4];
    #pragma unroll
    for (int mt = 0; mt < 2; mt++)
        #pragma unroll
        for (int nt = 0; nt < 4; nt++)
            #pragma unroll
            for (int r = 0; r < 4; r++) acc[mt][nt][r] = 0.f;

    load_stage(abase, 0);

    #pragma unroll 1
    for (int h = 0; h < Hc; h++) {
        const int p = h & 1;
        if (h < Hc - 1) {
            load_stage(abase + (1 - p) * STAGE_BYTES, h + 1);
            cp_wait<1>();
        } else {
            cp_wait<0>();
        }
        __syncthreads();

        const uint32_t Ab = abase + p * STAGE_BYTES;
        const uint32_t Bb = Ab + A_BYTES;

        uint32_t sim[2][4][2];
        #pragma unroll
        for (int mt = 0; mt < 2; mt++)
            #pragma unroll
            for (int nt = 0; nt < 4; nt++) {
                sim[mt][nt][0] = 0u;
                sim[mt][nt][1] = 0u;
            }

        #pragma unroll
        for (int k = 0; k < 4; k++) {
            uint32_t afr[2][4];
            #pragma unroll
            for (int mt = 0; mt < 2; mt++) {
                uint32_t off = (uint32_t)(a_row + mt * 16) * 128 + (k * 2 + a_sh) * 16;
                uint32_t sw = off ^ ((off >> 3) & 0x70);
                ldsm_x4(afr[mt], Ab + sw);
            }
            uint32_t bfr[4][2];
            #pragma unroll
            for (int ntp = 0; ntp < 2; ntp++) {
                uint32_t off = (uint32_t)(b_row + ntp * 16) * 128 + (k * 2 + b_sh) * 16;
                uint32_t sw = off ^ ((off >> 3) & 0x70);
                uint32_t r4[4];
                ldsm_x4(r4, Bb + sw);
                bfr[ntp * 2 + 0][0] = r4[0]; bfr[ntp * 2 + 0][1] = r4[1];
                bfr[ntp * 2 + 1][0] = r4[2]; bfr[ntp * 2 + 1][1] = r4[3];
            }
            #pragma unroll
            for (int mt = 0; mt < 2; mt++)
                #pragma unroll
                for (int nt = 0; nt < 4; nt++)
                    mma_f16acc(sim[mt][nt], afr[mt], bfr[nt]);
        }

        #pragma unroll
        for (int mt = 0; mt < 2; mt++)
            #pragma unroll
            for (int nt = 0; nt < 4; nt++) {
                #pragma unroll
                for (int half = 0; half < 2; half++) {
                    float2 f = __half22float2(
                        *reinterpret_cast<__half2*>(&sim[mt][nt][half]));
                    float t0 = tanh_fast(f.x * 0.5f);
                    float t1 = tanh_fast(f.y * 0.5f);
                    acc[mt][nt][half * 2 + 0] =
                        fmaf(0.5f, t0, acc[mt][nt][half * 2 + 0]);
                    acc[mt][nt][half * 2 + 1] =
                        fmaf(0.5f, t1, acc[mt][nt][half * 2 + 1]);
                }
            }

        __syncthreads();
    }

    // epilogue: adj = acc/8 + 0.5; teacher tg-rows = (col < N1c)
    const int g = lane >> 2;
    const int tig = lane & 3;
    #pragma unroll
    for (int mt = 0; mt < 2; mt++) {
        int gn0 = n0 + wm * 32 + mt * 16 + g;
        #pragma unroll
        for (int nt = 0; nt < 4; nt++) {
            int gm = m0 + wn * 32 + nt * 8 + tig * 2;
            if (gm < NNc) {
                float tv = (gm < N1c) ? 1.0f : 0.0f;
                if (gn0 < NNc) {
                    float2 v = make_float2(fmaf(acc[mt][nt][0], 0.125f, 0.5f),
                                           fmaf(acc[mt][nt][1], 0.125f, 0.5f));
                    *(float2*)&adj[(size_t)gn0 * NNc + gm] = v;
                    if (gn0 >= N1c)
                        *(float2*)&teacher[(size_t)gn0 * NNc + gm] =
                            make_float2(tv, tv);
                }
                int gn1 = gn0 + 8;
                if (gn1 < NNc) {
                    float2 v = make_float2(fmaf(acc[mt][nt][2], 0.125f, 0.5f),
                                           fmaf(acc[mt][nt][3], 0.125f, 0.5f));
                    *(float2*)&adj[(size_t)gn1 * NNc + gm] = v;
                    if (gn1 >= N1c)
                        *(float2*)&teacher[(size_t)gn1 * NNc + gm] =
                            make_float2(tv, tv);
                }
            }
        }
    }
}

// =====================================================================
// launch: embed -> adj on default stream; knn chain on s2.
// fill_tg deleted (fused into adj epilogue); topk owns lm teacher rows.
// =====================================================================
extern "C" void kernel_launch(void* const* d_in, const int* in_sizes, int n_in,
                              void* d_out, int out_size) {
    (void)in_sizes; (void)n_in; (void)out_size;
    const float* lm_X     = (const float*)d_in[0];
    const float* lm_Y     = (const float*)d_in[1];
    const float* tg_X     = (const float*)d_in[2];
    const float* lm_delay = (const float*)d_in[4];
    const float* tg_delay = (const float*)d_in[5];
    const float* W_emb    = (const float*)d_in[6];
    const float* b_emb    = (const float*)d_in[7];
    const float* w1       = (const float*)d_in[8];
    const float* w2       = (const float*)d_in[9];

    float* out     = (float*)d_out;
    float* y_pred  = out;                       // [2000, 2]
    float* adj     = out + 4000;                // [4000, 4000]
    float* teacher = adj + (size_t)NNc * NNc;   // [4000, 4000]

    static bool init = false;
    static cudaStream_t s2;
    static cudaEvent_t ef, e_join;
    const int ADJ_SMEM = 2 * STAGE_BYTES + 1024;  // 33792
    if (!init) {
        cudaFuncSetAttribute(adj_mm_kernel,
                             cudaFuncAttributeMaxDynamicSharedMemorySize, ADJ_SMEM);
        cudaStreamCreateWithFlags(&s2, cudaStreamNonBlocking);
        cudaEventCreateWithFlags(&ef,     cudaEventDisableTiming);
        cudaEventCreateWithFlags(&e_join, cudaEventDisableTiming);
        init = true;
    }

    // fork
    cudaEventRecord(ef, 0);
    cudaStreamWaitEvent(s2, ef, 0);

    // (0) embedding (default stream; adj depends on it)
    embed_kernel<<<512, 256>>>(lm_X, tg_X, lm_delay, tg_delay,
                               W_emb, b_emb, w1, w2);
    // knn branch on s2: sq -> xt -> d2 -> topk (topk writes lm teacher rows)
    sq_kernel<<<8, 256, 0, s2>>>(lm_X);
    xt_kernel<<<(Ec * MPADc + 255) / 256, 256, 0, s2>>>(lm_X);
    d2_kernel<<<528, 256, 0, s2>>>();
    topk_kernel<<<N1c, 256, 0, s2>>>(lm_Y, y_pred, teacher);
    cudaEventRecord(e_join, s2);
    // big adjacency GEMM (also writes teacher tg-rows) — last
    adj_mm_kernel<<<dim3(63, 63), 128, ADJ_SMEM>>>(adj, teacher);

    // join
    cudaStreamWaitEvent(0, e_join, 0);
}